// round 2
// baseline (speedup 1.0000x reference)
#include <cuda_runtime.h>
#include <cstdint>

#define N_TYPES 20
#define LMAX    13
#define DV      64
#define BATCH   16
#define TPB     192   // = DV*3, one thread per (v,d) output lane

__device__ const int d_res_len[N_TYPES] = {3,4,5,5,6,6,6,7,7,7,7,7,8,8,8,9,10,10,11,13};
__device__ int g_starts[4096];

// One-block exclusive prefix scan of residue lengths -> g_starts
__global__ void posmix_scan_kernel(const int* __restrict__ seq, int n_res) {
    __shared__ int ps[1024];
    int t = threadIdx.x;
    int i0 = 2*t, i1 = 2*t + 1;
    int l0 = (i0 < n_res) ? d_res_len[seq[i0]] : 0;
    int l1 = (i1 < n_res) ? d_res_len[seq[i1]] : 0;
    ps[t] = l0 + l1;
    __syncthreads();
    for (int off = 1; off < 1024; off <<= 1) {
        int v = ps[t];
        int a = (t >= off) ? ps[t - off] : 0;
        __syncthreads();
        ps[t] = v + a;
        __syncthreads();
    }
    int excl = (t == 0) ? 0 : ps[t - 1];
    if (i0 < n_res) g_starts[i0] = excl;
    if (i1 < n_res) g_starts[i1] = excl + l0;
}

#define FMA16(w)                                                    \
    do {                                                            \
        acc[0]  = fmaf((w), q0.x, acc[0]);                          \
        acc[1]  = fmaf((w), q0.y, acc[1]);                          \
        acc[2]  = fmaf((w), q0.z, acc[2]);                          \
        acc[3]  = fmaf((w), q0.w, acc[3]);                          \
        acc[4]  = fmaf((w), q1.x, acc[4]);                          \
        acc[5]  = fmaf((w), q1.y, acc[5]);                          \
        acc[6]  = fmaf((w), q1.z, acc[6]);                          \
        acc[7]  = fmaf((w), q1.w, acc[7]);                          \
        acc[8]  = fmaf((w), q2.x, acc[8]);                          \
        acc[9]  = fmaf((w), q2.y, acc[9]);                          \
        acc[10] = fmaf((w), q2.z, acc[10]);                         \
        acc[11] = fmaf((w), q2.w, acc[11]);                         \
        acc[12] = fmaf((w), q3.x, acc[12]);                         \
        acc[13] = fmaf((w), q3.y, acc[13]);                         \
        acc[14] = fmaf((w), q3.z, acc[14]);                         \
        acc[15] = fmaf((w), q3.w, acc[15]);                         \
    } while (0)

__global__ __launch_bounds__(TPB)
void posmix_kernel(const float* __restrict__ pos_atm,
                   const float* __restrict__ pos_amn,
                   const float* __restrict__ W_amn,
                   const float* __restrict__ W_atm,
                   const int*   __restrict__ seq,
                   float* __restrict__ out,
                   int atoms, int n_res)
{
    // diff_s[(l*3+d)*20 + b] : stride 20 floats (80B) keeps float4 alignment
    // and avoids the d0/d2 32-word bank alias of a stride-16 layout.
    __shared__ float diff_s[LMAX * 3 * 20];

    const int n   = blockIdx.x;
    const int tp  = seq[n];
    const int L   = d_res_len[tp];
    const int st  = g_starts[n];
    const int tid = threadIdx.x;
    const int v   = tid / 3;
    const int d   = tid - 3 * v;

    // Cooperative diff computation: diffs[b][l][dd] -> smem [l][dd][b]
    const int tot = BATCH * L * 3;
    for (int i = tid; i < tot; i += TPB) {
        int b  = i / (L * 3);
        int r  = i - b * (L * 3);
        int l  = r / 3;
        int dd = r - 3 * l;
        float pa = pos_atm[((size_t)b * atoms + st + l) * 3 + dd];
        float pm = pos_amn[((size_t)b * n_res + n) * 3 + dd];
        diff_s[(l * 3 + dd) * 20 + b] = pa - pm;
    }
    __syncthreads();

    // ---- x_v_atm: out[b][st+m][v][d] = sum_l W_atm[tp][m][v][l] * diff[b][l][d]
    const float* Wt = W_atm + (size_t)tp * LMAX * DV * LMAX;
    for (int m = 0; m < L; ++m) {
        const float* wrow = Wt + ((size_t)m * DV + v) * LMAX;
        float acc[BATCH];
        #pragma unroll
        for (int b = 0; b < BATCH; ++b) acc[b] = 0.f;
        for (int l = 0; l < L; ++l) {
            float w = __ldg(wrow + l);
            const float4* dp = reinterpret_cast<const float4*>(diff_s + (l * 3 + d) * 20);
            float4 q0 = dp[0], q1 = dp[1], q2 = dp[2], q3 = dp[3];
            FMA16(w);
        }
        size_t a = (size_t)(st + m);
        #pragma unroll
        for (int b = 0; b < BATCH; ++b)
            out[((size_t)b * atoms + a) * (DV * 3) + tid] = acc[b];
    }

    // ---- x_v_amn: out2[b][n][v][d] = sum_l W_amn[tp][v][l] * diff[b][l][d]
    {
        const float* wrow = W_amn + ((size_t)tp * DV + v) * LMAX;
        float acc[BATCH];
        #pragma unroll
        for (int b = 0; b < BATCH; ++b) acc[b] = 0.f;
        for (int l = 0; l < L; ++l) {
            float w = __ldg(wrow + l);
            const float4* dp = reinterpret_cast<const float4*>(diff_s + (l * 3 + d) * 20);
            float4 q0 = dp[0], q1 = dp[1], q2 = dp[2], q3 = dp[3];
            FMA16(w);
        }
        size_t amn_off = (size_t)BATCH * atoms * DV * 3;
        #pragma unroll
        for (int b = 0; b < BATCH; ++b)
            out[amn_off + ((size_t)b * n_res + n) * (DV * 3) + tid] = acc[b];
    }
}

extern "C" void kernel_launch(void* const* d_in, const int* in_sizes, int n_in,
                              void* d_out, int out_size)
{
    const float* pos_atm = (const float*)d_in[0];
    const float* pos_amn = (const float*)d_in[1];
    const float* W_amn   = (const float*)d_in[2];
    const float* W_atm   = (const float*)d_in[3];
    const int*   seq     = (const int*)d_in[4];

    const int n_res = in_sizes[4];                    // 2048
    const int atoms = in_sizes[0] / (BATCH * 3);      // 15036

    float* out = (float*)d_out;

    posmix_scan_kernel<<<1, 1024>>>(seq, n_res);
    posmix_kernel<<<n_res, TPB>>>(pos_atm, pos_amn, W_amn, W_atm, seq, out,
                                  atoms, n_res);
}

// round 4
// speedup vs baseline: 1.2774x; 1.2774x over previous
#include <cuda_runtime.h>
#include <cstdint>

#define N_TYPES 20
#define LMAX    13
#define DV      64
#define BATCH   16
#define TPB     192   // = DV*3, one thread per (v,d) output lane
#define MT      4     // m-tile

__device__ const int d_res_len[N_TYPES] = {3,4,5,5,6,6,6,7,7,7,7,7,8,8,8,9,10,10,11,13};
__device__ int g_starts[4096];

// One-block exclusive prefix scan of residue lengths -> g_starts
__global__ void posmix_scan_kernel(const int* __restrict__ seq, int n_res) {
    __shared__ int ps[1024];
    int t = threadIdx.x;
    int i0 = 2*t, i1 = 2*t + 1;
    int l0 = (i0 < n_res) ? d_res_len[seq[i0]] : 0;
    int l1 = (i1 < n_res) ? d_res_len[seq[i1]] : 0;
    ps[t] = l0 + l1;
    __syncthreads();
    for (int off = 1; off < 1024; off <<= 1) {
        int v = ps[t];
        int a = (t >= off) ? ps[t - off] : 0;
        __syncthreads();
        ps[t] = v + a;
        __syncthreads();
    }
    int excl = (t == 0) ? 0 : ps[t - 1];
    if (i0 < n_res) g_starts[i0] = excl;
    if (i1 < n_res) g_starts[i1] = excl + l0;
}

__device__ __forceinline__ void fma16(float* acc, float wv,
                                      float4 q0, float4 q1, float4 q2, float4 q3)
{
    acc[0]  = fmaf(wv, q0.x, acc[0]);
    acc[1]  = fmaf(wv, q0.y, acc[1]);
    acc[2]  = fmaf(wv, q0.z, acc[2]);
    acc[3]  = fmaf(wv, q0.w, acc[3]);
    acc[4]  = fmaf(wv, q1.x, acc[4]);
    acc[5]  = fmaf(wv, q1.y, acc[5]);
    acc[6]  = fmaf(wv, q1.z, acc[6]);
    acc[7]  = fmaf(wv, q1.w, acc[7]);
    acc[8]  = fmaf(wv, q2.x, acc[8]);
    acc[9]  = fmaf(wv, q2.y, acc[9]);
    acc[10] = fmaf(wv, q2.z, acc[10]);
    acc[11] = fmaf(wv, q2.w, acc[11]);
    acc[12] = fmaf(wv, q3.x, acc[12]);
    acc[13] = fmaf(wv, q3.y, acc[13]);
    acc[14] = fmaf(wv, q3.z, acc[14]);
    acc[15] = fmaf(wv, q3.w, acc[15]);
}

__global__ __launch_bounds__(TPB)
void posmix_kernel(const float* __restrict__ pos_atm,
                   const float* __restrict__ pos_amn,
                   const float* __restrict__ W_amn,
                   const float* __restrict__ W_atm,
                   const int*   __restrict__ seq,
                   float* __restrict__ out,
                   int atoms, int n_res)
{
    // diff_s[(l*3+d)*20 + b] : stride 20 floats (80B) keeps float4 alignment
    // and avoids the d0/d2 32-word bank alias of a stride-16 layout.
    __shared__ float diff_s[LMAX * 3 * 20];

    const int n   = blockIdx.x;
    const int tp  = seq[n];
    const int L   = d_res_len[tp];
    const int st  = g_starts[n];
    const int tid = threadIdx.x;
    const int v   = tid / 3;
    const int d   = tid - 3 * v;

    // Cooperative diff computation: diffs[b][l][dd] -> smem [l][dd][b]
    const int tot = BATCH * L * 3;
    for (int i = tid; i < tot; i += TPB) {
        int b  = i / (L * 3);
        int r  = i - b * (L * 3);
        int l  = r / 3;
        int dd = r - 3 * l;
        float pa = pos_atm[((size_t)b * atoms + st + l) * 3 + dd];
        float pm = pos_amn[((size_t)b * n_res + n) * 3 + dd];
        diff_s[(l * 3 + dd) * 20 + b] = pa - pm;
    }
    __syncthreads();

    const float* Wt      = W_atm + (size_t)tp * LMAX * DV * LMAX;
    const float* Wa_row  = W_amn + ((size_t)tp * DV + v) * LMAX;
    const size_t amn_off = (size_t)BATCH * atoms * (DV * 3);
    const size_t bstride_atm = (size_t)atoms * (DV * 3);
    const size_t bstride_amn = (size_t)n_res * (DV * 3);

    const int M = L + 1;  // L atm output rows + 1 amn row (folded as m == L)

    for (int mb = 0; mb < M; mb += MT) {
        const float* rows[MT];
        size_t obase[MT];
        size_t obstr[MT];
        bool   act[MT];
        #pragma unroll
        for (int j = 0; j < MT; ++j) {
            int m = mb + j;
            if (m < L) {
                rows[j]  = Wt + ((size_t)m * DV + v) * LMAX;
                obase[j] = (size_t)(st + m) * (DV * 3) + tid;
                obstr[j] = bstride_atm;
                act[j]   = true;
            } else if (m == L) {
                rows[j]  = Wa_row;
                obase[j] = amn_off + (size_t)n * (DV * 3) + tid;
                obstr[j] = bstride_amn;
                act[j]   = true;
            } else {
                rows[j]  = Wa_row;   // safe dummy read, result discarded
                obase[j] = 0;
                obstr[j] = 0;
                act[j]   = false;
            }
        }

        float acc0[BATCH], acc1[BATCH], acc2[BATCH], acc3[BATCH];
        #pragma unroll
        for (int b = 0; b < BATCH; ++b) {
            acc0[b] = 0.f; acc1[b] = 0.f; acc2[b] = 0.f; acc3[b] = 0.f;
        }

        for (int l = 0; l < L; ++l) {
            const float4* dp = reinterpret_cast<const float4*>(diff_s + (l * 3 + d) * 20);
            float4 q0 = dp[0], q1 = dp[1], q2 = dp[2], q3 = dp[3];
            float w0 = __ldg(rows[0] + l);
            float w1 = __ldg(rows[1] + l);
            float w2 = __ldg(rows[2] + l);
            float w3 = __ldg(rows[3] + l);
            fma16(acc0, w0, q0, q1, q2, q3);
            fma16(acc1, w1, q0, q1, q2, q3);
            fma16(acc2, w2, q0, q1, q2, q3);
            fma16(acc3, w3, q0, q1, q2, q3);
        }

        if (act[0]) {
            #pragma unroll
            for (int b = 0; b < BATCH; ++b) out[obase[0] + b * obstr[0]] = acc0[b];
        }
        if (act[1]) {
            #pragma unroll
            for (int b = 0; b < BATCH; ++b) out[obase[1] + b * obstr[1]] = acc1[b];
        }
        if (act[2]) {
            #pragma unroll
            for (int b = 0; b < BATCH; ++b) out[obase[2] + b * obstr[2]] = acc2[b];
        }
        if (act[3]) {
            #pragma unroll
            for (int b = 0; b < BATCH; ++b) out[obase[3] + b * obstr[3]] = acc3[b];
        }
    }
}

extern "C" void kernel_launch(void* const* d_in, const int* in_sizes, int n_in,
                              void* d_out, int out_size)
{
    const float* pos_atm = (const float*)d_in[0];
    const float* pos_amn = (const float*)d_in[1];
    const float* W_amn   = (const float*)d_in[2];
    const float* W_atm   = (const float*)d_in[3];
    const int*   seq     = (const int*)d_in[4];

    const int n_res = in_sizes[4];                    // 2048
    const int atoms = in_sizes[0] / (BATCH * 3);      // 15036

    float* out = (float*)d_out;

    posmix_scan_kernel<<<1, 1024>>>(seq, n_res);
    posmix_kernel<<<n_res, TPB>>>(pos_atm, pos_amn, W_amn, W_atm, seq, out,
                                  atoms, n_res);
}